// round 14
// baseline (speedup 1.0000x reference)
#include <cuda_runtime.h>
#include <cuda_fp16.h>
#include <stdint.h>

#define S_LEN   1370
#define B_SZ    8
#define D_MODEL 1024
#define H_NUM   16
#define HD      64
#define M_TOT   (B_SZ * S_LEN)   // 10960
#define LOG2E   1.4426950408889634f

// pre-converted GEMM operands (single fp16)
__device__ __half gX[(size_t)M_TOT * D_MODEL];
__device__ __half gW[3ull * D_MODEL * D_MODEL];
// projected Q/K/V in fp16, [B,H,S,HD]; Q pre-scaled by 0.125*log2(e)
__device__ __half g_Q[(size_t)M_TOT * D_MODEL];
__device__ __half g_K[(size_t)M_TOT * D_MODEL];
__device__ __half g_V[(size_t)M_TOT * D_MODEL];

// ---------------------------------------------------------------------------
// helpers
// ---------------------------------------------------------------------------
__device__ __forceinline__ uint32_t smem_u32(const void* p) {
    return (uint32_t)__cvta_generic_to_shared(p);
}
__device__ __forceinline__ void cp16(uint32_t dst, const void* src, int sz) {
    asm volatile("cp.async.cg.shared.global [%0], [%1], 16, %2;"
                 :: "r"(dst), "l"(src), "r"(sz) : "memory");
}
__device__ __forceinline__ void cp_commit() {
    asm volatile("cp.async.commit_group;" ::: "memory");
}
__device__ __forceinline__ void cp_wait0() {
    asm volatile("cp.async.wait_group 0;" ::: "memory");
}
__device__ __forceinline__ void ldm_x4(uint32_t& r0, uint32_t& r1, uint32_t& r2, uint32_t& r3,
                                       uint32_t addr) {
    asm volatile("ldmatrix.sync.aligned.m8n8.x4.shared.b16 {%0,%1,%2,%3}, [%4];"
                 : "=r"(r0), "=r"(r1), "=r"(r2), "=r"(r3) : "r"(addr));
}
__device__ __forceinline__ void ldm_x4t(uint32_t& r0, uint32_t& r1, uint32_t& r2, uint32_t& r3,
                                        uint32_t addr) {
    asm volatile("ldmatrix.sync.aligned.m8n8.x4.trans.shared.b16 {%0,%1,%2,%3}, [%4];"
                 : "=r"(r0), "=r"(r1), "=r"(r2), "=r"(r3) : "r"(addr));
}
__device__ __forceinline__ void mma16h(float* c, const uint32_t* a, uint32_t b0, uint32_t b1) {
    asm volatile(
        "mma.sync.aligned.m16n8k16.row.col.f32.f16.f16.f32 "
        "{%0,%1,%2,%3},{%4,%5,%6,%7},{%8,%9},{%0,%1,%2,%3};\n"
        : "+f"(c[0]), "+f"(c[1]), "+f"(c[2]), "+f"(c[3])
        : "r"(a[0]), "r"(a[1]), "r"(a[2]), "r"(a[3]), "r"(b0), "r"(b1));
}
__device__ __forceinline__ uint32_t h2pack(float lo, float hi) {
    __half2 h = __floats2half2_rn(lo, hi);
    return *reinterpret_cast<uint32_t*>(&h);
}
__device__ __forceinline__ float ex2(float x) {
    float y;
    asm("ex2.approx.f32 %0, %1;" : "=f"(y) : "f"(x));
    return y;
}
__device__ __forceinline__ uint32_t ex2h2(uint32_t x) {
    uint32_t y;
    asm("ex2.approx.f16x2 %0, %1;" : "=r"(y) : "r"(x));
    return y;
}
__device__ __forceinline__ __half2 u2h(uint32_t x) {
    return *reinterpret_cast<__half2*>(&x);
}
__device__ __forceinline__ uint32_t h2u(__half2 x) {
    return *reinterpret_cast<uint32_t*>(&x);
}

// ---------------------------------------------------------------------------
// Pre-convert fp32 -> fp16, single fused launch.
// ---------------------------------------------------------------------------
#define N4X (M_TOT * D_MODEL / 4)          // 2,805,760
#define N4W (D_MODEL * D_MODEL / 4)        // 262,144 = 2^18

__global__ void conv_all(const float* __restrict__ X,
                         const float* __restrict__ w0,
                         const float* __restrict__ w1,
                         const float* __restrict__ w2)
{
    int i = blockIdx.x * 256 + threadIdx.x;
    if (i >= N4X + 3 * N4W) return;
    const float* src;
    __half* dst;
    int idx;
    if (i < N4X) {
        src = X; dst = gX; idx = i;
    } else {
        int j = i - N4X;
        int plane = j >> 18;
        idx = j & (N4W - 1);
        src = (plane == 0) ? w0 : (plane == 1) ? w1 : w2;
        dst = gW + (size_t)plane * D_MODEL * D_MODEL;
    }
    float4 v = reinterpret_cast<const float4*>(src)[idx];
    uint32_t h0 = __half_as_ushort(__float2half_rn(v.x)) |
                  ((uint32_t)__half_as_ushort(__float2half_rn(v.y)) << 16);
    uint32_t h1 = __half_as_ushort(__float2half_rn(v.z)) |
                  ((uint32_t)__half_as_ushort(__float2half_rn(v.w)) << 16);
    reinterpret_cast<uint2*>(dst)[idx] = make_uint2(h0, h1);
}

// ---------------------------------------------------------------------------
// QKV projection: 128x128 tile, 256 threads (8 warps, 2x4), warp tile 64x32,
// K slab 64 (16 iterations — halves per-slab sync/issue overhead share),
// cp.async double-buffered (issue AFTER barrier: race-free), 2 CTAs/SM.
// ---------------------------------------------------------------------------
#define GPITCH  144                  // 64 fp16 = 128B data + 16B pad
#define GTILEB  (128 * GPITCH)       // 18432 per 128x64 tile
#define GBUFSZ  (2 * GTILEB)         // A, B = 36864
#define GEMM_SMEM (2 * GBUFSZ)       // 73728 (double buffer)

__global__ __launch_bounds__(256, 2) void qkv_fp16(
    const float* __restrict__ bq, const float* __restrict__ bk,
    const float* __restrict__ bv)
{
    extern __shared__ char smem[];
    const uint32_t sb = smem_u32(smem);

    const int z = blockIdx.z;
    const float* bias = (z == 0) ? bq : (z == 1) ? bk : bv;
    __half* out = (z == 0) ? g_Q : (z == 1) ? g_K : g_V;
    const float scale = (z == 0) ? 0.125f * LOG2E : 1.0f;
    const __half* W = gW + (size_t)z * D_MODEL * D_MODEL;

    const int tid  = threadIdx.x;
    const int lane = tid & 31;
    const int wid  = tid >> 5;
    const int wm   = wid >> 2;        // 0..1 : 64-row strip
    const int wn   = wid & 3;         // 0..3 : 32-col strip
    const int g    = lane >> 2;
    const int tig  = lane & 3;
    const int mat  = lane >> 3;
    const int mr   = lane & 7;

    const int m0 = blockIdx.y * 128;
    const int n0 = blockIdx.x * 128;

    // staging: 128 rows x 128B per tile; 2 threads/row, 64B (4 cp16) each
    const int srow = tid >> 1;        // 0..127
    const int sch  = (tid & 1) * 64;  // byte offset 0 or 64

    const int gm = m0 + srow;
    const int szA = (gm < M_TOT) ? 16 : 0;
    const size_t arow_off = (size_t)min(gm, M_TOT - 1) * D_MODEL;
    const size_t brow_off = (size_t)(n0 + srow) * D_MODEL;

    float c[4][4][4];
#pragma unroll
    for (int mf = 0; mf < 4; mf++)
#pragma unroll
        for (int nf = 0; nf < 4; nf++)
#pragma unroll
            for (int cc = 0; cc < 4; cc++) c[mf][nf][cc] = 0.0f;

    auto issue = [&](int s) {
        const int k0 = s * 64;
        uint32_t d0 = sb + (s & 1) * GBUFSZ + (uint32_t)srow * GPITCH + sch;
        const char* sA = (const char*)(gX + arow_off + k0) + sch;
        const char* sB = (const char*)(W + brow_off + k0) + sch;
#pragma unroll
        for (int q = 0; q < 4; q++) {
            cp16(d0 + q * 16,          sA + q * 16, szA);
            cp16(d0 + GTILEB + q * 16, sB + q * 16, 16);
        }
    };

    issue(0); cp_commit();

    for (int s = 0; s < 16; s++) {
        cp_wait0();
        __syncthreads();
        // prefetch AFTER barrier: buffer (s+1)&1 was fully consumed at slab s-1
        if (s + 1 < 16) { issue(s + 1); cp_commit(); }

        const uint32_t base = sb + (s & 1) * GBUFSZ;
#pragma unroll
        for (int t = 0; t < 4; t++) {
            uint32_t af[4][4];
#pragma unroll
            for (int mf = 0; mf < 4; mf++) {
                int arow = wm * 64 + mf * 16 + (mat & 1) * 8 + mr;
                uint32_t koff = t * 32 + (mat >> 1) * 16;
                uint32_t addr = base + (uint32_t)arow * GPITCH + koff;
                ldm_x4(af[mf][0], af[mf][1], af[mf][2], af[mf][3], addr);
            }
            uint32_t bf[4][2];
#pragma unroll
            for (int nfp = 0; nfp < 2; nfp++) {
                int nrow = wn * 32 + nfp * 16 + (mat >> 1) * 8 + mr;
                uint32_t koff = t * 32 + (mat & 1) * 16;
                uint32_t addr = base + GTILEB + (uint32_t)nrow * GPITCH + koff;
                ldm_x4(bf[2*nfp][0], bf[2*nfp][1], bf[2*nfp+1][0], bf[2*nfp+1][1],
                       addr);
            }
#pragma unroll
            for (int mf = 0; mf < 4; mf++)
#pragma unroll
                for (int nf = 0; nf < 4; nf++)
                    mma16h(c[mf][nf], af[mf], bf[nf][0], bf[nf][1]);
        }
    }

    // epilogue: bias + scale, fp16 scatter into [B,H,S,HD]
#pragma unroll
    for (int mf = 0; mf < 4; mf++) {
#pragma unroll
        for (int nf = 0; nf < 4; nf++) {
            int n = n0 + wn * 32 + nf * 8 + 2 * tig;
            int h = n >> 6, d = n & 63;
            float bv0 = __ldg(bias + n), bv1 = __ldg(bias + n + 1);
#pragma unroll
            for (int half = 0; half < 2; half++) {
                int m = m0 + wm * 64 + mf * 16 + g + half * 8;
                if (m < M_TOT) {
                    int bb = m / S_LEN;
                    int ss = m - bb * S_LEN;
                    __half2 hv = __floats2half2_rn(
                        (c[mf][nf][half * 2 + 0] + bv0) * scale,
                        (c[mf][nf][half * 2 + 1] + bv1) * scale);
                    *reinterpret_cast<__half2*>(
                        out + (((size_t)(bb * H_NUM + h) * S_LEN + ss) * HD + d)) = hv;
                }
            }
        }
    }
}

// ---------------------------------------------------------------------------
// Flash attention, fp16 m16n8k16 (unchanged from R13 best).
// CTA = 128 queries, 4 warps x two 16-row query tiles. Softmax in half2
// domain: pack once, hmax2 trees, packed 2-shuffle max, HSUB2, ex2.f16x2.
// ---------------------------------------------------------------------------
#define NEG_BIG (-30000.0f)
#define APITCH  144                   // bytes per smem row (64 fp16 + 8 pad)
#define KVSTG   9216                  // one 64-row K or V stage
#define ATTN_SMEM 36864

__global__ __launch_bounds__(128) void attn_fp16(float* __restrict__ out)
{
    __shared__ char asmem[ATTN_SMEM];
    const uint32_t sbase = smem_u32(asmem);

    const int h  = blockIdx.y;
    const int b  = blockIdx.z;
    const int qt = blockIdx.x;
    const int tid  = threadIdx.x;
    const int lane = tid & 31;
    const int w    = tid >> 5;
    const int g    = lane >> 2;
    const int tig  = lane & 3;
    const int mat  = lane >> 3;
    const int mr   = lane & 7;

    const size_t base = (size_t)(b * H_NUM + h) * S_LEN * HD;
    const __half* Qb = g_Q + base;
    const __half* Kb = g_K + base;
    const __half* Vb = g_V + base;

    // ---- stage Q (128 rows) into [0,18432), consume into registers ----
#pragma unroll
    for (int p = 0; p < 8; p++) {
        int idx = tid + 128 * p;       // 0..1023
        int row = idx >> 3;
        int ch  = idx & 7;
        int qi = qt * 128 + row;
        int sz = (qi < S_LEN) ? 16 : 0;
        const char* src = (const char*)(Qb + (size_t)min(qi, S_LEN - 1) * HD) + ch * 16;
        cp16(sbase + (uint32_t)row * APITCH + ch * 16, src, sz);
    }
    cp_commit();
    cp_wait0();
    __syncthreads();

    uint32_t qa[2][4][4];
#pragma unroll
    for (int u = 0; u < 2; u++)
#pragma unroll
        for (int ks = 0; ks < 4; ks++) {
            uint32_t addr = sbase
                + (uint32_t)(w * 32 + u * 16 + (mat & 1) * 8 + mr) * APITCH
                + ks * 32 + (mat >> 1) * 16;
            ldm_x4(qa[u][ks][0], qa[u][ks][1], qa[u][ks][2], qa[u][ks][3], addr);
        }
    __syncthreads();   // Q reads done; region reusable as K stages

    auto issue_kv = [&](int kt, int bb) {
#pragma unroll
        for (int p = 0; p < 4; p++) {
            int idx = tid + 128 * p;
            int row = idx >> 3;
            int ch  = idx & 7;
            int ki = kt * 64 + row;
            int sz = (ki < S_LEN) ? 16 : 0;
            size_t roff = (size_t)min(ki, S_LEN - 1) * HD;
            cp16(sbase + bb * KVSTG + (uint32_t)row * APITCH + ch * 16,
                 (const char*)(Kb + roff) + ch * 16, sz);
            cp16(sbase + 18432 + bb * KVSTG + (uint32_t)row * APITCH + ch * 16,
                 (const char*)(Vb + roff) + ch * 16, sz);
        }
    };

    issue_kv(0, 0);
    cp_commit();

    const uint32_t koffb = (uint32_t)((mat >> 1) * 8 + mr) * APITCH + (mat & 1) * 16;
    const uint32_t voffb = (uint32_t)((mat & 1) * 8 + mr) * APITCH + (mat >> 1) * 16;

    float oc[2][8][4];
    float l1[2] = {0.f, 0.f}, l2[2] = {0.f, 0.f};
#pragma unroll
    for (int u = 0; u < 2; u++)
#pragma unroll
        for (int nf = 0; nf < 8; nf++)
#pragma unroll
            for (int cc = 0; cc < 4; cc++) oc[u][nf][cc] = 0.0f;
    float m1[2] = {NEG_BIG, NEG_BIG}, m2[2] = {NEG_BIG, NEG_BIG};

    const int ntiles = (S_LEN + 63) / 64;    // 22
    for (int kt = 0; kt < ntiles; kt++) {
        cp_wait0();
        __syncthreads();
        if (kt + 1 < ntiles) { issue_kv(kt + 1, (kt + 1) & 1); cp_commit(); }

        const int rem = min(64, S_LEN - kt * 64);
        const uint32_t sbK = sbase + (kt & 1) * KVSTG;
        const uint32_t sbV = sbase + 18432 + (kt & 1) * KVSTG;

        // ---- S = Q K^T (log2-domain) ----
        float sc[2][8][4];
#pragma unroll
        for (int u = 0; u < 2; u++)
#pragma unroll
            for (int nf = 0; nf < 8; nf++)
#pragma unroll
                for (int cc = 0; cc < 4; cc++) sc[u][nf][cc] = 0.0f;

#pragma unroll
        for (int ks = 0; ks < 4; ks++) {
#pragma unroll
            for (int nf2 = 0; nf2 < 4; nf2++) {
                uint32_t r0, rr1, rr2, rr3;
                uint32_t addr = sbK + koffb + (uint32_t)(nf2 * 16) * APITCH + ks * 32;
                ldm_x4(r0, rr1, rr2, rr3, addr);
#pragma unroll
                for (int u = 0; u < 2; u++) {
                    mma16h(sc[u][2 * nf2],     qa[u][ks], r0,  rr1);
                    mma16h(sc[u][2 * nf2 + 1], qa[u][ks], rr2, rr3);
                }
            }
        }

        // ---- softmax in half2 domain ----
        uint32_t pp[2][8][2];
#pragma unroll
        for (int u = 0; u < 2; u++) {
            if (rem < 64) {
#pragma unroll
                for (int nf = 0; nf < 8; nf++) {
                    int col = nf * 8 + 2 * tig;
                    if (col     >= rem) { sc[u][nf][0] = NEG_BIG; sc[u][nf][2] = NEG_BIG; }
                    if (col + 1 >= rem) { sc[u][nf][1] = NEG_BIG; sc[u][nf][3] = NEG_BIG; }
                }
            }

            __half2 sh0[8], sh1[8];
#pragma unroll
            for (int nf = 0; nf < 8; nf++) {
                sh0[nf] = u2h(h2pack(sc[u][nf][0], sc[u][nf][1]));
                sh1[nf] = u2h(h2pack(sc[u][nf][2], sc[u][nf][3]));
            }

            __half2 t0 = __hmax2(
                __hmax2(__hmax2(sh0[0], sh0[1]), __hmax2(sh0[2], sh0[3])),
                __hmax2(__hmax2(sh0[4], sh0[5]), __hmax2(sh0[6], sh0[7])));
            __half2 t1 = __hmax2(
                __hmax2(__hmax2(sh1[0], sh1[1]), __hmax2(sh1[2], sh1[3])),
                __hmax2(__hmax2(sh1[4], sh1[5]), __hmax2(sh1[6], sh1[7])));
            __half2 mm = __halves2half2(__hmax(__low2half(t0), __high2half(t0)),
                                        __hmax(__low2half(t1), __high2half(t1)));
            mm = __hmax2(mm, u2h(__shfl_xor_sync(0xffffffffu, h2u(mm), 1)));
            mm = __hmax2(mm, u2h(__shfl_xor_sync(0xffffffffu, h2u(mm), 2)));
            float rmax1 = __low2float(mm);
            float rmax2 = __high2float(mm);

            float nm1 = fmaxf(m1[u], rmax1);
            float nm2 = fmaxf(m2[u], rmax2);

            bool moved = (nm1 > m1[u]) || (nm2 > m2[u]);
            if (__any_sync(0xffffffffu, moved)) {
                float corr1 = ex2(m1[u] - nm1);
                float corr2 = ex2(m2[u] - nm2);
#pragma unroll
                for (int nf = 0; nf < 8; nf++) {
                    oc[u][nf][0] *= corr1; oc[u][nf][1] *= corr1;
                    oc[u][nf][2] *= corr2; oc[u][nf][3] *= corr2;
                }
                l1[u] *= corr1;
                l2[u] *= corr2;
                m1[u] = nm1; m2[u] = nm2;
            }

            __half2 mb1 = __float2half2_rn(m1[u]);
            __half2 mb2 = __float2half2_rn(m2[u]);
#pragma unroll
            for (int nf = 0; nf < 8; nf++) {
                pp[u][nf][0] = ex2h2(h2u(__hsub2(sh0[nf], mb1)));
                pp[u][nf][1] = ex2h2(h2u(__hsub2(sh1[nf], mb2)));
            }

            __half2 s1 = __hadd2(
                __hadd2(__hadd2(u2h(pp[u][0][0]), u2h(pp[u][1][0])),
                        __hadd2(u2h(pp[u][2][0]), u2h(pp[u][3][0]))),
                __hadd2(__hadd2(u2h(pp[u][4][0]), u2h(pp[u][5][0])),
                        __hadd2(u2h(pp[u][6][0]), u2h(pp[u][7][0]))));
            __half2 s2 = __hadd2(
                __hadd2(__hadd2(u2h(pp[u][0][1]), u2h(pp[u][1][1])),
                        __hadd2(u2h(pp[u][2][1]), u2h(pp[u][3][1]))),
                __hadd2(__hadd2(u2h(pp[u][4][1]), u2h(pp[u][5][1])),
                        __hadd2(u2h(pp[u][6][1]), u2h(pp[u][7][1]))));
            float2 f1 = __half22float2(s1);
            float2 f2 = __half22float2(s2);
            l1[u] += f1.x + f1.y;
            l2[u] += f2.x + f2.y;
        }

        // ---- O += P V (P already fp16-packed in pp) ----
#pragma unroll
        for (int ks = 0; ks < 4; ks++) {
#pragma unroll
            for (int nf2 = 0; nf2 < 4; nf2++) {
                uint32_t r0, rr1, rr2, rr3;
                uint32_t addr = sbV + voffb + (uint32_t)(ks * 16) * APITCH + nf2 * 32;
                ldm_x4t(r0, rr1, rr2, rr3, addr);
#pragma unroll
                for (int u = 0; u < 2; u++) {
                    mma16h(oc[u][2 * nf2],     &pp[u][2 * ks][0], r0,  rr1);
                    mma16h(oc[u][2 * nf2 + 1], &pp[u][2 * ks][0], rr2, rr3);
                }
            }
        }
    }

    // ---- final row-sum reduction + normalize + write [B,S,H*HD] fp32 ----
#pragma unroll
    for (int u = 0; u < 2; u++) {
        float s1 = l1[u], s2 = l2[u];
        s1 += __shfl_xor_sync(0xffffffffu, s1, 1);
        s1 += __shfl_xor_sync(0xffffffffu, s1, 2);
        s2 += __shfl_xor_sync(0xffffffffu, s2, 1);
        s2 += __shfl_xor_sync(0xffffffffu, s2, 2);
        const int r1 = qt * 128 + w * 32 + u * 16 + g;
        const int r2 = r1 + 8;
        float inv1 = 1.0f / s1;
        float inv2 = 1.0f / s2;
#pragma unroll
        for (int nf = 0; nf < 8; nf++) {
            int d = nf * 8 + 2 * tig;
            if (r1 < S_LEN) {
                float2 v; v.x = oc[u][nf][0] * inv1; v.y = oc[u][nf][1] * inv1;
                *reinterpret_cast<float2*>(
                    out + (size_t)(b * S_LEN + r1) * D_MODEL + h * HD + d) = v;
            }
            if (r2 < S_LEN) {
                float2 v; v.x = oc[u][nf][2] * inv2; v.y = oc[u][nf][3] * inv2;
                *reinterpret_cast<float2*>(
                    out + (size_t)(b * S_LEN + r2) * D_MODEL + h * HD + d) = v;
            }
        }
    }
}

// ---------------------------------------------------------------------------
extern "C" void kernel_launch(void* const* d_in, const int* in_sizes, int n_in,
                              void* d_out, int out_size)
{
    const float* X  = (const float*)d_in[0];
    const float* Wq = (const float*)d_in[1];
    const float* bq = (const float*)d_in[2];
    const float* Wk = (const float*)d_in[3];
    const float* bk = (const float*)d_in[4];
    const float* Wv = (const float*)d_in[5];
    const float* bv = (const float*)d_in[6];
    float* out = (float*)d_out;

    static int once = 0;
    if (!once) {
        cudaFuncSetAttribute(qkv_fp16, cudaFuncAttributeMaxDynamicSharedMemorySize, GEMM_SMEM);
        once = 1;
    }

    const int ntot = N4X + 3 * N4W;
    conv_all<<<(ntot + 255) / 256, 256>>>(X, Wq, Wk, Wv);

    dim3 g1(D_MODEL / 128, (M_TOT + 127) / 128, 3);
    qkv_fp16<<<g1, 256, GEMM_SMEM>>>(bq, bk, bv);

    dim3 g2((S_LEN + 127) / 128, H_NUM, B_SZ);
    attn_fp16<<<g2, 128>>>(out);
}

// round 15
// speedup vs baseline: 1.0817x; 1.0817x over previous
#include <cuda_runtime.h>
#include <cuda_fp16.h>
#include <stdint.h>

#define S_LEN   1370
#define B_SZ    8
#define D_MODEL 1024
#define H_NUM   16
#define HD      64
#define M_TOT   (B_SZ * S_LEN)   // 10960
#define LOG2E   1.4426950408889634f

// pre-converted GEMM operands (single fp16)
__device__ __half gX[(size_t)M_TOT * D_MODEL];
__device__ __half gW[3ull * D_MODEL * D_MODEL];
// projected Q/K/V in fp16, [B,H,S,HD]; Q pre-scaled by 0.125*log2(e)
__device__ __half g_Q[(size_t)M_TOT * D_MODEL];
__device__ __half g_K[(size_t)M_TOT * D_MODEL];
__device__ __half g_V[(size_t)M_TOT * D_MODEL];

// ---------------------------------------------------------------------------
// helpers
// ---------------------------------------------------------------------------
__device__ __forceinline__ uint32_t smem_u32(const void* p) {
    return (uint32_t)__cvta_generic_to_shared(p);
}
__device__ __forceinline__ void cp16(uint32_t dst, const void* src, int sz) {
    asm volatile("cp.async.cg.shared.global [%0], [%1], 16, %2;"
                 :: "r"(dst), "l"(src), "r"(sz) : "memory");
}
__device__ __forceinline__ void cp_commit() {
    asm volatile("cp.async.commit_group;" ::: "memory");
}
__device__ __forceinline__ void cp_wait1() {
    asm volatile("cp.async.wait_group 1;" ::: "memory");
}
__device__ __forceinline__ void cp_wait0() {
    asm volatile("cp.async.wait_group 0;" ::: "memory");
}
__device__ __forceinline__ void ldm_x4(uint32_t& r0, uint32_t& r1, uint32_t& r2, uint32_t& r3,
                                       uint32_t addr) {
    asm volatile("ldmatrix.sync.aligned.m8n8.x4.shared.b16 {%0,%1,%2,%3}, [%4];"
                 : "=r"(r0), "=r"(r1), "=r"(r2), "=r"(r3) : "r"(addr));
}
__device__ __forceinline__ void ldm_x4t(uint32_t& r0, uint32_t& r1, uint32_t& r2, uint32_t& r3,
                                        uint32_t addr) {
    asm volatile("ldmatrix.sync.aligned.m8n8.x4.trans.shared.b16 {%0,%1,%2,%3}, [%4];"
                 : "=r"(r0), "=r"(r1), "=r"(r2), "=r"(r3) : "r"(addr));
}
__device__ __forceinline__ void mma16h(float* c, const uint32_t* a, uint32_t b0, uint32_t b1) {
    asm volatile(
        "mma.sync.aligned.m16n8k16.row.col.f32.f16.f16.f32 "
        "{%0,%1,%2,%3},{%4,%5,%6,%7},{%8,%9},{%0,%1,%2,%3};\n"
        : "+f"(c[0]), "+f"(c[1]), "+f"(c[2]), "+f"(c[3])
        : "r"(a[0]), "r"(a[1]), "r"(a[2]), "r"(a[3]), "r"(b0), "r"(b1));
}
__device__ __forceinline__ uint32_t h2pack(float lo, float hi) {
    __half2 h = __floats2half2_rn(lo, hi);
    return *reinterpret_cast<uint32_t*>(&h);
}
__device__ __forceinline__ float ex2(float x) {
    float y;
    asm("ex2.approx.f32 %0, %1;" : "=f"(y) : "f"(x));
    return y;
}
__device__ __forceinline__ uint32_t ex2h2(uint32_t x) {
    uint32_t y;
    asm("ex2.approx.f16x2 %0, %1;" : "=r"(y) : "r"(x));
    return y;
}
__device__ __forceinline__ __half2 u2h(uint32_t x) {
    return *reinterpret_cast<__half2*>(&x);
}
__device__ __forceinline__ uint32_t h2u(__half2 x) {
    return *reinterpret_cast<uint32_t*>(&x);
}

// ---------------------------------------------------------------------------
// Pre-convert fp32 -> fp16, single fused launch, 2 uint4 per thread.
// Pairs never straddle an X/W-plane boundary (N4X, N4W both even).
// ---------------------------------------------------------------------------
#define N4X (M_TOT * D_MODEL / 4)          // 2,805,760
#define N4W (D_MODEL * D_MODEL / 4)        // 262,144 = 2^18

__global__ void conv_all(const float* __restrict__ X,
                         const float* __restrict__ w0,
                         const float* __restrict__ w1,
                         const float* __restrict__ w2)
{
    int p = blockIdx.x * 256 + threadIdx.x;          // pair index
    int i = 2 * p;
    if (i >= N4X + 3 * N4W) return;
    const float* src;
    __half* dst;
    int idx;
    if (i < N4X) {
        src = X; dst = gX; idx = i;
    } else {
        int j = i - N4X;
        int plane = j >> 18;
        idx = j & (N4W - 1);
        src = (plane == 0) ? w0 : (plane == 1) ? w1 : w2;
        dst = gW + (size_t)plane * D_MODEL * D_MODEL;
    }
#pragma unroll
    for (int e = 0; e < 2; e++) {
        float4 v = reinterpret_cast<const float4*>(src)[idx + e];
        uint32_t h0 = __half_as_ushort(__float2half_rn(v.x)) |
                      ((uint32_t)__half_as_ushort(__float2half_rn(v.y)) << 16);
        uint32_t h1 = __half_as_ushort(__float2half_rn(v.z)) |
                      ((uint32_t)__half_as_ushort(__float2half_rn(v.w)) << 16);
        reinterpret_cast<uint2*>(dst)[idx + e] = make_uint2(h0, h1);
    }
}

// ---------------------------------------------------------------------------
// QKV projection (R13 config — best measured): 128x128 tile, 256 threads
// (8 warps, 2x4), warp tile 64x32, K slab 32, cp.async 3-stage pipelined
// (issue AFTER barrier: race-free), 2 CTAs/SM.
// Epilogue: C routed through smem for 128B-coalesced STG.128 stores.
// ---------------------------------------------------------------------------
#define PITCH  80
#define TILEB  10240                 // one 128x32 fp16 tile (pitch 80)
#define BUFSZ  (2 * TILEB)           // A, B
#define NSTG   3
#define GEMM_SMEM (NSTG * BUFSZ)     // 61440
#define CPITCH 272                   // C-tile smem pitch (bank-conflict-free)

__global__ __launch_bounds__(256, 2) void qkv_fp16(
    const float* __restrict__ bq, const float* __restrict__ bk,
    const float* __restrict__ bv)
{
    extern __shared__ char smem[];
    const uint32_t sb = smem_u32(smem);

    const int z = blockIdx.z;
    const float* bias = (z == 0) ? bq : (z == 1) ? bk : bv;
    __half* out = (z == 0) ? g_Q : (z == 1) ? g_K : g_V;
    const float scale = (z == 0) ? 0.125f * LOG2E : 1.0f;
    const __half* W = gW + (size_t)z * D_MODEL * D_MODEL;

    const int tid  = threadIdx.x;
    const int lane = tid & 31;
    const int wid  = tid >> 5;
    const int wm   = wid >> 2;        // 0..1 : 64-row strip
    const int wn   = wid & 3;         // 0..3 : 32-col strip
    const int g    = lane >> 2;
    const int tig  = lane & 3;
    const int mat  = lane >> 3;
    const int mr   = lane & 7;

    const int m0 = blockIdx.y * 128;
    const int n0 = blockIdx.x * 128;

    const int srow = tid >> 1;        // 0..127
    const int sch  = (tid & 1) * 32;  // byte offset 0 or 32

    const int gm = m0 + srow;
    const int szA = (gm < M_TOT) ? 16 : 0;
    const size_t arow_off = (size_t)min(gm, M_TOT - 1) * D_MODEL;
    const size_t brow_off = (size_t)(n0 + srow) * D_MODEL;

    float c[4][4][4];
#pragma unroll
    for (int mf = 0; mf < 4; mf++)
#pragma unroll
        for (int nf = 0; nf < 4; nf++)
#pragma unroll
            for (int cc = 0; cc < 4; cc++) c[mf][nf][cc] = 0.0f;

    auto issue = [&](int s) {
        const int k0 = s * 32;
        uint32_t d0 = sb + (s % NSTG) * BUFSZ + (uint32_t)srow * PITCH + sch;
        const char* sA = (const char*)(gX + arow_off + k0) + sch;
        const char* sB = (const char*)(W + brow_off + k0) + sch;
        cp16(d0,              sA,      szA);
        cp16(d0 + 16,         sA + 16, szA);
        cp16(d0 + TILEB,      sB,      16);
        cp16(d0 + TILEB + 16, sB + 16, 16);
    };

    issue(0); cp_commit();
    issue(1); cp_commit();

    for (int s = 0; s < 32; s++) {
        if (s + 1 < 32) cp_wait1(); else cp_wait0();
        __syncthreads();
        if (s + 2 < 32) { issue(s + 2); cp_commit(); }

        const uint32_t base = sb + (s % NSTG) * BUFSZ;
#pragma unroll
        for (int t = 0; t < 2; t++) {
            uint32_t af[4][4];
#pragma unroll
            for (int mf = 0; mf < 4; mf++) {
                int arow = wm * 64 + mf * 16 + (mat & 1) * 8 + mr;
                uint32_t koff = t * 32 + (mat >> 1) * 16;
                uint32_t addr = base + (uint32_t)arow * PITCH + koff;
                ldm_x4(af[mf][0], af[mf][1], af[mf][2], af[mf][3], addr);
            }
            uint32_t bf[4][2];
#pragma unroll
            for (int nfp = 0; nfp < 2; nfp++) {
                int nrow = wn * 32 + nfp * 16 + (mat >> 1) * 8 + mr;
                uint32_t koff = t * 32 + (mat & 1) * 16;
                uint32_t addr = base + (uint32_t)nrow * PITCH + koff;
                ldm_x4(bf[2*nfp][0], bf[2*nfp][1], bf[2*nfp+1][0], bf[2*nfp+1][1],
                       addr + TILEB);
            }
#pragma unroll
            for (int mf = 0; mf < 4; mf++)
#pragma unroll
                for (int nf = 0; nf < 4; nf++)
                    mma16h(c[mf][nf], af[mf], bf[nf][0], bf[nf][1]);
        }
    }

    // ---- epilogue: bias + scale -> smem C tile -> coalesced STG.128 ----
    __syncthreads();   // all warps out of mainloop; smem reusable
#pragma unroll
    for (int mf = 0; mf < 4; mf++) {
#pragma unroll
        for (int nf = 0; nf < 4; nf++) {
            int n = n0 + wn * 32 + nf * 8 + 2 * tig;
            int nloc = wn * 32 + nf * 8 + 2 * tig;
            float bv0 = __ldg(bias + n), bv1 = __ldg(bias + n + 1);
#pragma unroll
            for (int half = 0; half < 2; half++) {
                int rloc = wm * 64 + mf * 16 + g + half * 8;
                __half2 hv = __floats2half2_rn(
                    (c[mf][nf][half * 2 + 0] + bv0) * scale,
                    (c[mf][nf][half * 2 + 1] + bv1) * scale);
                *reinterpret_cast<__half2*>(
                    smem + (uint32_t)rloc * CPITCH + nloc * 2) = hv;
            }
        }
    }
    __syncthreads();

    // 128 rows x 16 chunks of 16B; 256 threads x 8 iterations, coalesced
#pragma unroll
    for (int it = 0; it < 8; it++) {
        int t = tid + it * 256;        // 0..2047
        int r = t >> 4;                // 0..127
        int ch = t & 15;               // 0..15
        int m = m0 + r;
        if (m < M_TOT) {
            int bb = m / S_LEN;
            int ss = m - bb * S_LEN;
            int hh = (n0 >> 6) + (ch >> 3);     // head index
            int c8 = ch & 7;                    // 16B chunk within head row
            uint4 v = *reinterpret_cast<uint4*>(smem + (uint32_t)r * CPITCH + ch * 16);
            *reinterpret_cast<uint4*>(
                out + ((size_t)(bb * H_NUM + hh) * S_LEN + ss) * HD + c8 * 8) = v;
        }
    }
}

// ---------------------------------------------------------------------------
// Flash attention, fp16 m16n8k16 (R13 best, unchanged).
// ---------------------------------------------------------------------------
#define NEG_BIG (-30000.0f)
#define APITCH  144                   // bytes per smem row (64 fp16 + 8 pad)
#define KVSTG   9216                  // one 64-row K or V stage
#define ATTN_SMEM 36864

__global__ __launch_bounds__(128) void attn_fp16(float* __restrict__ out)
{
    __shared__ char asmem[ATTN_SMEM];
    const uint32_t sbase = smem_u32(asmem);

    const int h  = blockIdx.y;
    const int b  = blockIdx.z;
    const int qt = blockIdx.x;
    const int tid  = threadIdx.x;
    const int lane = tid & 31;
    const int w    = tid >> 5;
    const int g    = lane >> 2;
    const int tig  = lane & 3;
    const int mat  = lane >> 3;
    const int mr   = lane & 7;

    const size_t base = (size_t)(b * H_NUM + h) * S_LEN * HD;
    const __half* Qb = g_Q + base;
    const __half* Kb = g_K + base;
    const __half* Vb = g_V + base;

#pragma unroll
    for (int p = 0; p < 8; p++) {
        int idx = tid + 128 * p;
        int row = idx >> 3;
        int ch  = idx & 7;
        int qi = qt * 128 + row;
        int sz = (qi < S_LEN) ? 16 : 0;
        const char* src = (const char*)(Qb + (size_t)min(qi, S_LEN - 1) * HD) + ch * 16;
        cp16(sbase + (uint32_t)row * APITCH + ch * 16, src, sz);
    }
    cp_commit();
    cp_wait0();
    __syncthreads();

    uint32_t qa[2][4][4];
#pragma unroll
    for (int u = 0; u < 2; u++)
#pragma unroll
        for (int ks = 0; ks < 4; ks++) {
            uint32_t addr = sbase
                + (uint32_t)(w * 32 + u * 16 + (mat & 1) * 8 + mr) * APITCH
                + ks * 32 + (mat >> 1) * 16;
            ldm_x4(qa[u][ks][0], qa[u][ks][1], qa[u][ks][2], qa[u][ks][3], addr);
        }
    __syncthreads();

    auto issue_kv = [&](int kt, int bb) {
#pragma unroll
        for (int p = 0; p < 4; p++) {
            int idx = tid + 128 * p;
            int row = idx >> 3;
            int ch  = idx & 7;
            int ki = kt * 64 + row;
            int sz = (ki < S_LEN) ? 16 : 0;
            size_t roff = (size_t)min(ki, S_LEN - 1) * HD;
            cp16(sbase + bb * KVSTG + (uint32_t)row * APITCH + ch * 16,
                 (const char*)(Kb + roff) + ch * 16, sz);
            cp16(sbase + 18432 + bb * KVSTG + (uint32_t)row * APITCH + ch * 16,
                 (const char*)(Vb + roff) + ch * 16, sz);
        }
    };

    issue_kv(0, 0);
    cp_commit();

    const uint32_t koffb = (uint32_t)((mat >> 1) * 8 + mr) * APITCH + (mat & 1) * 16;
    const uint32_t voffb = (uint32_t)((mat & 1) * 8 + mr) * APITCH + (mat >> 1) * 16;

    float oc[2][8][4];
    float l1[2] = {0.f, 0.f}, l2[2] = {0.f, 0.f};
#pragma unroll
    for (int u = 0; u < 2; u++)
#pragma unroll
        for (int nf = 0; nf < 8; nf++)
#pragma unroll
            for (int cc = 0; cc < 4; cc++) oc[u][nf][cc] = 0.0f;
    float m1[2] = {NEG_BIG, NEG_BIG}, m2[2] = {NEG_BIG, NEG_BIG};

    const int ntiles = (S_LEN + 63) / 64;    // 22
    for (int kt = 0; kt < ntiles; kt++) {
        cp_wait0();
        __syncthreads();
        if (kt + 1 < ntiles) { issue_kv(kt + 1, (kt + 1) & 1); cp_commit(); }

        const int rem = min(64, S_LEN - kt * 64);
        const uint32_t sbK = sbase + (kt & 1) * KVSTG;
        const uint32_t sbV = sbase + 18432 + (kt & 1) * KVSTG;

        float sc[2][8][4];
#pragma unroll
        for (int u = 0; u < 2; u++)
#pragma unroll
            for (int nf = 0; nf < 8; nf++)
#pragma unroll
                for (int cc = 0; cc < 4; cc++) sc[u][nf][cc] = 0.0f;

#pragma unroll
        for (int ks = 0; ks < 4; ks++) {
#pragma unroll
            for (int nf2 = 0; nf2 < 4; nf2++) {
                uint32_t r0, rr1, rr2, rr3;
                uint32_t addr = sbK + koffb + (uint32_t)(nf2 * 16) * APITCH + ks * 32;
                ldm_x4(r0, rr1, rr2, rr3, addr);
#pragma unroll
                for (int u = 0; u < 2; u++) {
                    mma16h(sc[u][2 * nf2],     qa[u][ks], r0,  rr1);
                    mma16h(sc[u][2 * nf2 + 1], qa[u][ks], rr2, rr3);
                }
            }
        }

        uint32_t pp[2][8][2];
#pragma unroll
        for (int u = 0; u < 2; u++) {
            if (rem < 64) {
#pragma unroll
                for (int nf = 0; nf < 8; nf++) {
                    int col = nf * 8 + 2 * tig;
                    if (col     >= rem) { sc[u][nf][0] = NEG_BIG; sc[u][nf][2] = NEG_BIG; }
                    if (col + 1 >= rem) { sc[u][nf][1] = NEG_BIG; sc[u][nf][3] = NEG_BIG; }
                }
            }

            __half2 sh0[8], sh1[8];
#pragma unroll
            for (int nf = 0; nf < 8; nf++) {
                sh0[nf] = u2h(h2pack(sc[u][nf][0], sc[u][nf][1]));
                sh1[nf] = u2h(h2pack(sc[u][nf][2], sc[u][nf][3]));
            }

            __half2 t0 = __hmax2(
                __hmax2(__hmax2(sh0[0], sh0[1]), __hmax2(sh0[2], sh0[3])),
                __hmax2(__hmax2(sh0[4], sh0[5]), __hmax2(sh0[6], sh0[7])));
            __half2 t1 = __hmax2(
                __hmax2(__hmax2(sh1[0], sh1[1]), __hmax2(sh1[2], sh1[3])),
                __hmax2(__hmax2(sh1[4], sh1[5]), __hmax2(sh1[6], sh1[7])));
            __half2 mm = __halves2half2(__hmax(__low2half(t0), __high2half(t0)),
                                        __hmax(__low2half(t1), __high2half(t1)));
            mm = __hmax2(mm, u2h(__shfl_xor_sync(0xffffffffu, h2u(mm), 1)));
            mm = __hmax2(mm, u2h(__shfl_xor_sync(0xffffffffu, h2u(mm), 2)));
            float rmax1 = __low2float(mm);
            float rmax2 = __high2float(mm);

            float nm1 = fmaxf(m1[u], rmax1);
            float nm2 = fmaxf(m2[u], rmax2);

            bool moved = (nm1 > m1[u]) || (nm2 > m2[u]);
            if (__any_sync(0xffffffffu, moved)) {
                float corr1 = ex2(m1[u] - nm1);
                float corr2 = ex2(m2[u] - nm2);
#pragma unroll
                for (int nf = 0; nf < 8; nf++) {
                    oc[u][nf][0] *= corr1; oc[u][nf][1] *= corr1;
                    oc[u][nf][2] *= corr2; oc[u][nf][3] *= corr2;
                }
                l1[u] *= corr1;
                l2[u] *= corr2;
                m1[u] = nm1; m2[u] = nm2;
            }

            __half2 mb1 = __float2half2_rn(m1[u]);
            __half2 mb2 = __float2half2_rn(m2[u]);
#pragma unroll
            for (int nf = 0; nf < 8; nf++) {
                pp[u][nf][0] = ex2h2(h2u(__hsub2(sh0[nf], mb1)));
                pp[u][nf][1] = ex2h2(h2u(__hsub2(sh1[nf], mb2)));
            }

            __half2 s1 = __hadd2(
                __hadd2(__hadd2(u2h(pp[u][0][0]), u2h(pp[u][1][0])),
                        __hadd2(u2h(pp[u][2][0]), u2h(pp[u][3][0]))),
                __hadd2(__hadd2(u2h(pp[u][4][0]), u2h(pp[u][5][0])),
                        __hadd2(u2h(pp[u][6][0]), u2h(pp[u][7][0]))));
            __half2 s2 = __hadd2(
                __hadd2(__hadd2(u2h(pp[u][0][1]), u2h(pp[u][1][1])),
                        __hadd2(u2h(pp[u][2][1]), u2h(pp[u][3][1]))),
                __hadd2(__hadd2(u2h(pp[u][4][1]), u2h(pp[u][5][1])),
                        __hadd2(u2h(pp[u][6][1]), u2h(pp[u][7][1]))));
            float2 f1 = __half22float2(s1);
            float2 f2 = __half22float2(s2);
            l1[u] += f1.x + f1.y;
            l2[u] += f2.x + f2.y;
        }

#pragma unroll
        for (int ks = 0; ks < 4; ks++) {
#pragma unroll
            for (int nf2 = 0; nf2 < 4; nf2++) {
                uint32_t r0, rr1, rr2, rr3;
                uint32_t addr = sbV + voffb + (uint32_t)(ks * 16) * APITCH + nf2 * 32;
                ldm_x4t(r0, rr1, rr2, rr3, addr);
#pragma unroll
                for (int u = 0; u < 2; u++) {
                    mma16h(oc[u][2 * nf2],     &pp[u][2 * ks][0], r0,  rr1);
                    mma16h(oc[u][2 * nf2 + 1], &pp[u][2 * ks][0], rr2, rr3);
                }
            }
        }
    }

#pragma unroll
    for (int u = 0; u < 2; u++) {
        float s1 = l1[u], s2 = l2[u];
        s1 += __shfl_xor_sync(0xffffffffu, s1, 1);
        s1 += __shfl_xor_sync(0xffffffffu, s1, 2);
        s2 += __shfl_xor_sync(0xffffffffu, s2, 1);
        s2 += __shfl_xor_sync(0xffffffffu, s2, 2);
        const int r1 = qt * 128 + w * 32 + u * 16 + g;
        const int r2 = r1 + 8;
        float inv1 = 1.0f / s1;
        float inv2 = 1.0f / s2;
#pragma unroll
        for (int nf = 0; nf < 8; nf++) {
            int d = nf * 8 + 2 * tig;
            if (r1 < S_LEN) {
                float2 v; v.x = oc[u][nf][0] * inv1; v.y = oc[u][nf][1] * inv1;
                *reinterpret_cast<float2*>(
                    out + (size_t)(b * S_LEN + r1) * D_MODEL + h * HD + d) = v;
            }
            if (r2 < S_LEN) {
                float2 v; v.x = oc[u][nf][2] * inv2; v.y = oc[u][nf][3] * inv2;
                *reinterpret_cast<float2*>(
                    out + (size_t)(b * S_LEN + r2) * D_MODEL + h * HD + d) = v;
            }
        }
    }
}

// ---------------------------------------------------------------------------
extern "C" void kernel_launch(void* const* d_in, const int* in_sizes, int n_in,
                              void* d_out, int out_size)
{
    const float* X  = (const float*)d_in[0];
    const float* Wq = (const float*)d_in[1];
    const float* bq = (const float*)d_in[2];
    const float* Wk = (const float*)d_in[3];
    const float* bk = (const float*)d_in[4];
    const float* Wv = (const float*)d_in[5];
    const float* bv = (const float*)d_in[6];
    float* out = (float*)d_out;

    static int once = 0;
    if (!once) {
        cudaFuncSetAttribute(qkv_fp16, cudaFuncAttributeMaxDynamicSharedMemorySize, GEMM_SMEM);
        once = 1;
    }

    const int npairs = (N4X + 3 * N4W) / 2;
    conv_all<<<(npairs + 255) / 256, 256>>>(X, Wq, Wk, Wv);

    dim3 g1(D_MODEL / 128, (M_TOT + 127) / 128, 3);
    qkv_fp16<<<g1, 256, GEMM_SMEM>>>(bq, bk, bv);

    dim3 g2((S_LEN + 127) / 128, H_NUM, B_SZ);
    attn_fp16<<<g2, 128>>>(out);
}